// round 13
// baseline (speedup 1.0000x reference)
#include <cuda_runtime.h>
#include <math.h>

#define D        4096
#define KSEL     614              // int(4096 * 0.15)
#define THREADS  256
#define V4PT     4                // float4 per thread
#define NBIN     1024             // bins: b = u >> 21 (raw bits; <1024 iff positive)
#define CAP      768              // spec candidates: bins [507,509], lambda~508
#define TCAP     64               // top-2 candidates: bins >= 513 (x >= 2.5), lambda~25
#define SPEC_LO  507u             // bin(0.875)  -- histogram floor AND candidate lo
#define SPEC_HI  509u             // bin hi: covers values < 1.5
#define TOP2_BIN 513u             // bin(2.5)
#define FULL     0xFFFFFFFFu
#define GAIN     3.0f
#define NEG_INF  (-__int_as_float(0x7F800000))

// monotone float <-> uint mapping (slow path only)
__device__ __forceinline__ unsigned f2s(unsigned u) {
    return u ^ ((u & 0x80000000u) ? 0xFFFFFFFFu : 0x80000000u);
}
__device__ __forceinline__ float s2f(unsigned s) {
    unsigned u = (s & 0x80000000u) ? (s ^ 0x80000000u) : ~s;
    return __uint_as_float(u);
}

__global__ void __launch_bounds__(THREADS, 8)
diff_gated_topk_kernel(const float* __restrict__ x, float* __restrict__ out) {
    __shared__ unsigned hist[NBIN];        // [0..255] reused as L2 hist in fast path
    __shared__ unsigned cand[CAP];
    __shared__ unsigned candT[TCAP];
    __shared__ unsigned cand2[32];
    __shared__ unsigned s_ncand, s_nT, s_ncand2;
    __shared__ unsigned warp_off[THREADS / 32];
    __shared__ float    w_m1[THREADS / 32], w_m2[THREADS / 32];
    __shared__ unsigned s_binid, s_want, s_bin2, s_want2, s_thr;
    __shared__ float    s_thrf, s_gain;

    const int t    = threadIdx.x;
    const int lane = t & 31;
    const int warp = t >> 5;
    const size_t base = (size_t)blockIdx.x * D;

    const float4* in4  = (const float4*)(x + base);
    float4*       out4 = (float4*)(out + base);
    uint4*        h4   = (uint4*)hist;

    // ---- Phase 0 ----
    h4[t] = make_uint4(0, 0, 0, 0);
    if (t == 0) { s_ncand = 0; s_nT = 0; s_ncand2 = 0; s_binid = 0xFFFFFFFFu; }
    __syncthreads();

    // ---- Phase 1: floor-filtered histogram + candidate gathers (one scan) ----
#pragma unroll
    for (int i = 0; i < V4PT; i++) {
        float4 v = in4[t + i * THREADS];          // default caching: L1-resident for reuse
        unsigned u[4] = {__float_as_uint(v.x), __float_as_uint(v.y),
                         __float_as_uint(v.z), __float_as_uint(v.w)};
#pragma unroll
        for (int c = 0; c < 4; c++) {
            const unsigned b  = u[c] >> 21;
            const unsigned rb = b - SPEC_LO;      // wraps for b < SPEC_LO or negatives
            if (rb < (NBIN - SPEC_LO))            // only b in [507, 1023] counted
                atomicAdd(&hist[b], 1u);
            if (rb <= (SPEC_HI - SPEC_LO)) {      // threshold-bin candidates
                unsigned p = atomicAdd(&s_ncand, 1u);
                if (p < CAP) cand[p] = u[c];
            }
            if (b - TOP2_BIN < (NBIN - TOP2_BIN)) {  // top-2 candidates
                unsigned p = atomicAdd(&s_nT, 1u);
                if (p < TCAP) candT[p] = u[c];
            }
        }
    }
    __syncthreads();

    // ---- Phase 2: descending rank-KSEL scan (bins < 507 are zero, harmless) ----
    const int qb = 4 * (255 - t);                 // t=0 owns the TOP bins
    const uint4 hv = h4[255 - t];
    unsigned h[4] = {hv.x, hv.y, hv.z, hv.w};
    unsigned csum = h[0] + h[1] + h[2] + h[3];

    unsigned inc = csum;
#pragma unroll
    for (int o = 1; o < 32; o <<= 1) {
        unsigned n = __shfl_up_sync(FULL, inc, o);
        if (lane >= o) inc += n;
    }
    if (lane == 31) warp_off[warp] = inc;
    __syncthreads();

    if (t == 0) {
        unsigned run = 0;
#pragma unroll
        for (int w = 0; w < THREADS / 32; w++) {
            unsigned tt = warp_off[w];
            warp_off[w] = run;
            run += tt;
        }
    }
    __syncthreads();

    {
        const unsigned excl = warp_off[warp] + inc - csum;
        if (excl < KSEL && KSEL <= excl + csum) { // at most one thread
            unsigned cum = excl;
#pragma unroll
            for (int j = 3; j >= 0; j--) {
                unsigned c = h[j];
                if (cum + c >= KSEL) { s_binid = (unsigned)(qb + j); s_want = KSEL - cum; break; }
                cum += c;
            }
        }
    }
    __syncthreads();

    // ---- Slow-path check (uniform; ~never taken for Gaussian rows) ----
    const bool slow = (s_binid - SPEC_LO > (SPEC_HI - SPEC_LO))   // incl. sentinel / run<KSEL
                   || (s_ncand > CAP) || (s_nT < 2) || (s_nT > TCAP);

    if (slow) {
        // ===== exact generic path: full monotone-key histogram =====
        h4[t] = make_uint4(0, 0, 0, 0);
        if (t == 0) s_ncand = 0;
        __syncthreads();
        for (int i = 0; i < V4PT; i++) {
            float4 v = in4[t + i * THREADS];
            unsigned u[4] = {__float_as_uint(v.x), __float_as_uint(v.y),
                             __float_as_uint(v.z), __float_as_uint(v.w)};
            for (int c = 0; c < 4; c++)
                atomicAdd(&hist[f2s(u[c]) >> 22], 1u);
        }
        __syncthreads();
        if (t == 0) {
            unsigned cum = 0;
            for (int b = NBIN - 1; b >= 0; b--) {
                unsigned c = hist[b];
                if (cum + c >= KSEL) { s_binid = (unsigned)b; s_want = KSEL - cum; break; }
                cum += c;
            }
        }
        __syncthreads();
        // collect key-matching candidates + full top-2 reduce
        float m1 = NEG_INF, m2 = NEG_INF;
        const unsigned binid = s_binid;
        for (int i = 0; i < V4PT; i++) {
            float4 v = in4[t + i * THREADS];
            float f[4] = {v.x, v.y, v.z, v.w};
            for (int c = 0; c < 4; c++) {
                float hi = fmaxf(m1, f[c]);
                float lo = fminf(m1, f[c]);
                m2 = fmaxf(m2, lo);
                m1 = hi;
                unsigned key = f2s(__float_as_uint(f[c]));
                if ((key >> 22) == binid) {
                    unsigned p = atomicAdd(&s_ncand, 1u);
                    if (p < CAP) cand[p] = key;
                }
            }
        }
#pragma unroll
        for (int o = 16; o > 0; o >>= 1) {
            float a = __shfl_down_sync(FULL, m1, o);
            float b = __shfl_down_sync(FULL, m2, o);
            float hi = fmaxf(m1, a);
            float lo = fminf(m1, a);
            m2 = fmaxf(fmaxf(m2, b), lo);
            m1 = hi;
        }
        if (lane == 0) { w_m1[warp] = m1; w_m2[warp] = m2; }
        __syncthreads();
        if (t == 0) {
            float v1 = w_m1[0], v2 = w_m2[0];
#pragma unroll
            for (int w = 1; w < THREADS / 32; w++) {
                float a = w_m1[w], b = w_m2[w];
                float hi = fmaxf(v1, a);
                float lo = fminf(v1, a);
                v2 = fmaxf(fmaxf(v2, b), lo);
                v1 = hi;
            }
            s_gain = GAIN / (1.0f + __expf(-(v1 - v2))) + 1.0f;
        }
        __syncthreads();
        // exact quadratic rank-select (strided; covers all candidates)
        unsigned nc = s_ncand; if (nc > CAP) nc = CAP;
        const unsigned want = s_want;
        for (unsigned ci = t; ci < nc; ci += THREADS) {
            unsigned v = cand[ci];
            unsigned gt = 0, eq = 0;
            for (unsigned j = 0; j < nc; j++) {
                unsigned u = cand[j];
                gt += (u > v);
                eq += (u == v);
            }
            if (gt < want && gt + eq >= want) s_thrf = s2f(v);
        }
        __syncthreads();
    } else {
        // ===== fast path =====
        // ---- Phase 4a: zero L2 hist; warp 0 computes gain; build L2 hist ----
        hist[t] = 0;
        __syncthreads();

        const unsigned binid = s_binid;
        unsigned nc = s_ncand;                    // <= CAP guaranteed here

        if (warp == 0) {                          // gain from top-2 candidates
            unsigned nT = s_nT;                   // 2 <= nT <= TCAP
            float a = (lane < (int)nT)      ? __uint_as_float(candT[lane])      : NEG_INF;
            float b = (lane + 32 < (int)nT) ? __uint_as_float(candT[lane + 32]) : NEG_INF;
            float m1 = fmaxf(a, b);
            float m2 = fminf(a, b);
#pragma unroll
            for (int o = 16; o > 0; o >>= 1) {
                float aa = __shfl_down_sync(FULL, m1, o);
                float bb = __shfl_down_sync(FULL, m2, o);
                float hi = fmaxf(m1, aa);
                float lo = fminf(m1, aa);
                m2 = fmaxf(fmaxf(m2, bb), lo);
                m1 = hi;
            }
            if (lane == 0) s_gain = GAIN / (1.0f + __expf(-(m1 - m2))) + 1.0f;
        }

        for (unsigned ci = t; ci < nc; ci += THREADS) {
            unsigned u = cand[ci];
            if ((u >> 21) == binid) atomicAdd(&hist[(u >> 13) & 0xFFu], 1u);
        }
        __syncthreads();

        // ---- Phase 4b: locate L2 sub-bin (1 bin/thread, descending) ----
        {
            const int b2 = 255 - t;
            unsigned c2 = hist[b2];
            unsigned inc2 = c2;
#pragma unroll
            for (int o = 1; o < 32; o <<= 1) {
                unsigned n = __shfl_up_sync(FULL, inc2, o);
                if (lane >= o) inc2 += n;
            }
            if (lane == 31) warp_off[warp] = inc2;
            __syncthreads();
            unsigned woff = 0;
#pragma unroll
            for (int w = 0; w < THREADS / 32; w++)
                woff += (w < warp) ? warp_off[w] : 0;
            const unsigned excl2 = woff + inc2 - c2;
            const unsigned want = s_want;
            if (excl2 < want && want <= excl2 + c2) {
                s_bin2  = (unsigned)b2;
                s_want2 = want - excl2;
            }
        }
        __syncthreads();

        // ---- Phase 4c: exact select inside sub-bin (expected 1-2 candidates) ----
        {
            const unsigned bin2 = s_bin2;
            for (unsigned ci = t; ci < nc; ci += THREADS) {
                unsigned s = cand[ci];
                if ((s >> 21) == binid && ((s >> 13) & 0xFFu) == bin2) {
                    unsigned p = atomicAdd(&s_ncand2, 1u);
                    if (p < 32) cand2[p] = s;
                }
            }
        }
        __syncthreads();
        {
            unsigned nc2 = s_ncand2; if (nc2 > 32) nc2 = 32;
            const unsigned want2 = s_want2;
            if (t < (int)nc2) {
                unsigned v = cand2[t];
                unsigned gt = 0, eq = 0;
                for (unsigned j = 0; j < nc2; j++) {
                    unsigned u = cand2[j];
                    gt += (u > v);
                    eq += (u == v);
                }
                if (gt < want2 && gt + eq >= want2)
                    s_thrf = __uint_as_float(v);   // positive raw bits == float value
            }
        }
        __syncthreads();
    }

    // ---- Phase 5: re-read (L1-resident) + gated scaled write-out ----
    const float thr  = s_thrf;
    const float gain = s_gain;
#pragma unroll
    for (int i = 0; i < V4PT; i++) {
        float4 v = in4[t + i * THREADS];
        v.x = (v.x >= thr) ? v.x * gain : 0.0f;
        v.y = (v.y >= thr) ? v.y * gain : 0.0f;
        v.z = (v.z >= thr) ? v.z * gain : 0.0f;
        v.w = (v.w >= thr) ? v.w * gain : 0.0f;
        __stcs(&out4[t + i * THREADS], v);
    }
}

extern "C" void kernel_launch(void* const* d_in, const int* in_sizes, int n_in,
                              void* d_out, int out_size) {
    const float* x = (const float*)d_in[0];
    float* out = (float*)d_out;
    const int n_rows = in_sizes[0] / D;   // 16384
    diff_gated_topk_kernel<<<n_rows, THREADS>>>(x, out);
}

// round 14
// speedup vs baseline: 1.2181x; 1.2181x over previous
#include <cuda_runtime.h>
#include <math.h>

#define D        4096
#define KSEL     614              // int(4096 * 0.15)
#define THREADS  256
#define V4PT     4                // float4 per thread
#define SEG      128              // window candidates per warp (lambda~64, 8.5 sigma)
#define TSEG     16               // top-2 candidates per warp  (lambda~3.2, 7 sigma)
#define WLO      0.875f           // window lo  (k-th value = 1.036 +- 0.024)
#define WHI      1.5f             // window hi
#define TLO      2.5f             // top-2 gather floor
#define WLOBITS  0x3F600000u      // bits of 0.875f
#define FULL     0xFFFFFFFFu
#define GAIN     3.0f
#define NEG_INF  (-__int_as_float(0x7F800000))

// monotone float <-> uint mapping (slow path only)
__device__ __forceinline__ unsigned f2s(unsigned u) {
    return u ^ ((u & 0x80000000u) ? 0xFFFFFFFFu : 0x80000000u);
}
__device__ __forceinline__ float s2f(unsigned s) {
    unsigned u = (s & 0x80000000u) ? (s ^ 0x80000000u) : ~s;
    return __uint_as_float(u);
}

__global__ void __launch_bounds__(THREADS, 8)
diff_gated_topk_kernel(const float* __restrict__ x, float* __restrict__ out) {
    __shared__ unsigned hist[1024];          // 768 sub-bins + zero padding
    __shared__ unsigned candW[8 * SEG];      // per-warp window candidate segments
    __shared__ unsigned candT[8 * TSEG];     // per-warp top-2 candidate segments
    __shared__ unsigned cand2[32];
    __shared__ unsigned wctr[8], wctrT[8];
    __shared__ unsigned warp_off[8];
    __shared__ float    w_m1[8], w_m2[8];
    __shared__ unsigned s_cnthi, s_ncand2, s_bin2, s_want2;
    __shared__ float    s_thrf, s_gain;

    const int t    = threadIdx.x;
    const int lane = t & 31;
    const int warp = t >> 5;
    const size_t base = (size_t)blockIdx.x * D;

    const float4* in4  = (const float4*)(x + base);
    float4*       out4 = (float4*)(out + base);
    uint4*        h4   = (uint4*)hist;

    // ---- P0: zero sub-bin hist + counters ----
    h4[t] = make_uint4(0, 0, 0, 0);
    if (t < 8) { wctr[t] = 0; wctrT[t] = 0; }
    if (t == 0) { s_cnthi = 0; s_ncand2 = 0; }
    __syncthreads();

    // ---- P1: single row sweep: count >=WHI, gather window + top-2 candidates ----
    unsigned cnt = 0;
#pragma unroll
    for (int i = 0; i < V4PT; i++) {
        float4 v = in4[t + i * THREADS];       // default caching: L1-resident for reuse
        float f[4] = {v.x, v.y, v.z, v.w};
#pragma unroll
        for (int c = 0; c < 4; c++) {
            const float fv = f[c];
            if (fv >= WLO && fv < WHI) {       // window gather (12.5% of elements)
                unsigned p = atomicAdd(&wctr[warp], 1u);
                if (p < SEG) candW[(warp << 7) + p] = __float_as_uint(fv);
            }
            cnt += (fv >= WHI) ? 1u : 0u;      // exact rank offset above window
            if (fv >= TLO) {                   // top-2 gather (0.6% of elements)
                unsigned p = atomicAdd(&wctrT[warp], 1u);
                if (p < TSEG) candT[(warp << 4) + p] = __float_as_uint(fv);
            }
        }
    }
    cnt = __reduce_add_sync(FULL, cnt);
    if (lane == 0) atomicAdd(&s_cnthi, cnt);
    __syncthreads();

    // ---- P2: uniform validity check ----
    bool of = false;
    unsigned nc = 0, nT = 0;
#pragma unroll
    for (int w = 0; w < 8; w++) {
        unsigned c = wctr[w];  of |= (c > SEG);  nc += (c > SEG ? SEG : c);
        unsigned d = wctrT[w]; of |= (d > TSEG); nT += (d > TSEG ? TSEG : d);
    }
    const unsigned ch = s_cnthi;
    const bool slow = of || (nT < 2u) || (ch >= KSEL) || (ch + nc < KSEL);

    if (!slow) {
        // ================= fast path =================
        const unsigned want0 = KSEL - ch;      // rank wanted inside the window

        // ---- P3: warp0 computes gain; all warps build 768-bin hist over candidates ----
        if (warp == 0) {
            float m1 = NEG_INF, m2 = NEG_INF;
#pragma unroll
            for (int s = 0; s < 4; s++) {
                int slot = lane + 32 * s;
                bool ok = (unsigned)(slot & 15) < wctrT[slot >> 4];
                float a = ok ? __uint_as_float(candT[slot]) : NEG_INF;
                float hi = fmaxf(m1, a);
                float lo = fminf(m1, a);
                m2 = fmaxf(m2, lo);
                m1 = hi;
            }
#pragma unroll
            for (int o = 16; o > 0; o >>= 1) {
                float a = __shfl_down_sync(FULL, m1, o);
                float b = __shfl_down_sync(FULL, m2, o);
                float hi = fmaxf(m1, a);
                float lo = fminf(m1, a);
                m2 = fmaxf(fmaxf(m2, b), lo);
                m1 = hi;
            }
            if (lane == 0) s_gain = GAIN / (1.0f + __expf(-(m1 - m2))) + 1.0f;
        }
#pragma unroll
        for (int k = 0; k < (8 * SEG) / THREADS; k++) {
            int ci = t + k * THREADS;
            if ((unsigned)(ci & (SEG - 1)) < wctr[ci >> 7]) {
                unsigned u = candW[ci];
                atomicAdd(&hist[(u - WLOBITS) >> 13], 1u);
            }
        }
        __syncthreads();

        // ---- P4: descending rank scan over 1024 bins (768 live) ----
        const int qb = 4 * (255 - t);          // t=0 owns the TOP bins
        const uint4 hv = h4[255 - t];
        unsigned h[4] = {hv.x, hv.y, hv.z, hv.w};
        unsigned csum = h[0] + h[1] + h[2] + h[3];
        unsigned inc = csum;
#pragma unroll
        for (int o = 1; o < 32; o <<= 1) {
            unsigned n = __shfl_up_sync(FULL, inc, o);
            if (lane >= o) inc += n;
        }
        if (lane == 31) warp_off[warp] = inc;
        __syncthreads();
        if (t == 0) {
            unsigned run = 0;
#pragma unroll
            for (int w = 0; w < 8; w++) {
                unsigned tt = warp_off[w];
                warp_off[w] = run;
                run += tt;
            }
        }
        __syncthreads();
        {
            const unsigned excl = warp_off[warp] + inc - csum;
            if (excl < want0 && want0 <= excl + csum) {   // exactly one thread
                unsigned cum = excl;
#pragma unroll
                for (int j = 3; j >= 0; j--) {
                    unsigned c = h[j];
                    if (cum + c >= want0) { s_bin2 = (unsigned)(qb + j); s_want2 = want0 - cum; break; }
                    cum += c;
                }
            }
        }
        __syncthreads();

        // ---- P5: collect sub-bin candidates (expected ~1) ----
        {
            const unsigned bin2 = s_bin2;
#pragma unroll
            for (int k = 0; k < (8 * SEG) / THREADS; k++) {
                int ci = t + k * THREADS;
                if ((unsigned)(ci & (SEG - 1)) < wctr[ci >> 7]) {
                    unsigned u = candW[ci];
                    if (((u - WLOBITS) >> 13) == bin2) {
                        unsigned p = atomicAdd(&s_ncand2, 1u);
                        if (p < 32) cand2[p] = u;
                    }
                }
            }
        }
        __syncthreads();

        // ---- P6: exact select among sub-bin candidates ----
        {
            unsigned nc2 = s_ncand2; if (nc2 > 32) nc2 = 32;
            const unsigned want2 = s_want2;
            if (t < (int)nc2) {
                unsigned v = cand2[t];
                unsigned gt = 0, eq = 0;
                for (unsigned j = 0; j < nc2; j++) {
                    unsigned u = cand2[j];
                    gt += (u > v);
                    eq += (u == v);
                }
                if (gt < want2 && gt + eq >= want2)
                    s_thrf = __uint_as_float(v);   // positive bits == value order
            }
        }
        __syncthreads();
    } else {
        // ================= exact generic slow path (~never taken) =================
        h4[t] = make_uint4(0, 0, 0, 0);
        if (t == 0) s_ncand2 = 0;
        __syncthreads();
        for (int i = 0; i < V4PT; i++) {
            float4 v = in4[t + i * THREADS];
            unsigned u[4] = {__float_as_uint(v.x), __float_as_uint(v.y),
                             __float_as_uint(v.z), __float_as_uint(v.w)};
            for (int c = 0; c < 4; c++)
                atomicAdd(&hist[f2s(u[c]) >> 22], 1u);
        }
        __syncthreads();
        if (t == 0) {
            unsigned cum = 0;
            for (int b = 1023; b >= 0; b--) {
                unsigned c = hist[b];
                if (cum + c >= KSEL) { s_bin2 = (unsigned)b; s_want2 = KSEL - cum; break; }
                cum += c;
            }
        }
        __syncthreads();
        // collect key-matching candidates + full top-2 reduce
        float m1 = NEG_INF, m2 = NEG_INF;
        const unsigned binS = s_bin2;
        for (int i = 0; i < V4PT; i++) {
            float4 v = in4[t + i * THREADS];
            float f[4] = {v.x, v.y, v.z, v.w};
            for (int c = 0; c < 4; c++) {
                float hi = fmaxf(m1, f[c]);
                float lo = fminf(m1, f[c]);
                m2 = fmaxf(m2, lo);
                m1 = hi;
                unsigned key = f2s(__float_as_uint(f[c]));
                if ((key >> 22) == binS) {
                    unsigned p = atomicAdd(&s_ncand2, 1u);
                    if (p < 8 * SEG) candW[p] = key;
                }
            }
        }
#pragma unroll
        for (int o = 16; o > 0; o >>= 1) {
            float a = __shfl_down_sync(FULL, m1, o);
            float b = __shfl_down_sync(FULL, m2, o);
            float hi = fmaxf(m1, a);
            float lo = fminf(m1, a);
            m2 = fmaxf(fmaxf(m2, b), lo);
            m1 = hi;
        }
        if (lane == 0) { w_m1[warp] = m1; w_m2[warp] = m2; }
        __syncthreads();
        if (t == 0) {
            float v1 = w_m1[0], v2 = w_m2[0];
#pragma unroll
            for (int w = 1; w < 8; w++) {
                float a = w_m1[w], b = w_m2[w];
                float hi = fmaxf(v1, a);
                float lo = fminf(v1, a);
                v2 = fmaxf(fmaxf(v2, b), lo);
                v1 = hi;
            }
            s_gain = GAIN / (1.0f + __expf(-(v1 - v2))) + 1.0f;
        }
        __syncthreads();
        {
            unsigned ncS = s_ncand2; if (ncS > 8 * SEG) ncS = 8 * SEG;
            const unsigned wantS = s_want2;
            for (unsigned ci = t; ci < ncS; ci += THREADS) {
                unsigned v = candW[ci];
                unsigned gt = 0, eq = 0;
                for (unsigned j = 0; j < ncS; j++) {
                    unsigned u = candW[j];
                    gt += (u > v);
                    eq += (u == v);
                }
                if (gt < wantS && gt + eq >= wantS) s_thrf = s2f(v);
            }
        }
        __syncthreads();
    }

    // ---- P7: re-read (L1-resident) + gated scaled write-out ----
    const float thr  = s_thrf;
    const float gain = s_gain;
#pragma unroll
    for (int i = 0; i < V4PT; i++) {
        float4 v = in4[t + i * THREADS];
        v.x = (v.x >= thr) ? v.x * gain : 0.0f;
        v.y = (v.y >= thr) ? v.y * gain : 0.0f;
        v.z = (v.z >= thr) ? v.z * gain : 0.0f;
        v.w = (v.w >= thr) ? v.w * gain : 0.0f;
        __stcs(&out4[t + i * THREADS], v);
    }
}

extern "C" void kernel_launch(void* const* d_in, const int* in_sizes, int n_in,
                              void* d_out, int out_size) {
    const float* x = (const float*)d_in[0];
    float* out = (float*)d_out;
    const int n_rows = in_sizes[0] / D;   // 16384
    diff_gated_topk_kernel<<<n_rows, THREADS>>>(x, out);
}